// round 4
// baseline (speedup 1.0000x reference)
#include <cuda_runtime.h>

#define Nn     5000
#define TST    5024          // transposed buffer node stride
#define NF     33
#define NU     32
#define TENC   12
#define TDEC   12
#define BM     128
#define BK     32
#define MT     40            // ceil(5000/128)
#define KT     157           // ceil(5000/32)
#define SPLITK 11
#define GGRID  (MT*SPLITK)   // 440

#define AS_W   (BM*36)       // 4608 words per A stage
#define XS_W   (NF*36)       // 1188 words per X stage
#define NSTAGE 3
#define GEMM_SMEM (NSTAGE*(AS_W + XS_W)*4)   // 69552 bytes

// ------------- persistent device state (transposed: [feature][node]) -------------
__device__ float g_X0T[NF*TST];
__device__ float g_X1T[NF*TST];
__device__ float g_X2T[NF*TST];
__device__ float g_C0T[NF*TST];
__device__ float g_C1T[NF*TST];
__device__ float g_C2T[NF*TST];
__device__ float g_hT [NU*TST];
__device__ float g_uT [NU*TST];

// ------------- helpers -------------
__device__ __forceinline__ void cp16(void* dst, const void* src) {
    unsigned s = (unsigned)__cvta_generic_to_shared(dst);
    asm volatile("cp.async.cg.shared.global [%0], [%1], 16;\n" :: "r"(s), "l"(src));
}
// A loads: evict_last policy so adj pins in L2 across all 96 GEMMs
__device__ __forceinline__ void cp16pol(void* dst, const void* src, int bytes,
                                        unsigned long long pol) {
    unsigned s = (unsigned)__cvta_generic_to_shared(dst);
    asm volatile("cp.async.cg.shared.global.L2::cache_hint [%0], [%1], 16, %2, %3;\n"
                 :: "r"(s), "l"(src), "r"(bytes), "l"(pol));
}
__device__ __forceinline__ void ffma2(unsigned long long& acc,
                                      unsigned long long a, unsigned long long b) {
    asm("fma.rn.f32x2 %0, %1, %2, %0;" : "+l"(acc) : "l"(a), "l"(b));
}
__device__ __forceinline__ float sumb64(unsigned long long v) {
    float lo = __uint_as_float((unsigned)v);
    float hi = __uint_as_float((unsigned)(v >> 32));
    return lo + hi;
}

// ============================================================================
// Y^T += (A @ X)^T : A [5000x5000] row-major, X/Y transposed [33][TST].
// BM=128 rows, BK=32, 3-stage cp.async ring, split-K=11, atomicAdd epilogue.
// Thread tile: 2 rows (lane + 32q + 64*half) x 8 cols; cg==0 warps add col 32.
// ============================================================================
__global__ void __launch_bounds__(256, 3) gemmT(const float* __restrict__ A, int sel)
{
    extern __shared__ float sm[];
    float* as = sm;                    // [3][128][36]
    float* xs = sm + NSTAGE*AS_W;      // [3][33][36]

    const float* __restrict__ XT;
    float* __restrict__ YT;
    switch (sel) {
        case 0:  XT = g_X0T; YT = g_X1T; break;
        case 1:  XT = g_X1T; YT = g_X2T; break;
        case 2:  XT = g_C0T; YT = g_C1T; break;
        default: XT = g_C1T; YT = g_C2T; break;
    }

    unsigned long long pol;
    asm("createpolicy.fractional.L2::evict_last.b64 %0, 1.0;" : "=l"(pol));

    const int t    = threadIdx.x;
    const int rt   = blockIdx.x % MT;
    const int ck   = blockIdx.x / MT;
    const int row0 = rt * BM;
    const int tS   = (KT * ck)       / SPLITK;
    const int tE   = (KT * (ck + 1)) / SPLITK;
    const int w    = t >> 5, lane = t & 31;
    const int half = w >> 2, cg = w & 3;
    const int rb   = half * 64;
    const int c0   = cg * 8;

    // A loader: 128 rows x 32 k; thread -> row (t&127), k-half (t>>7)*16
    const int tr = t & 127, th = t >> 7;
    const int grow = row0 + tr;
    const float* aRow = A + (long)(grow < Nn ? grow : Nn - 1) * Nn;
    const int xc = t >> 3, xch = t & 7;

    auto load_tile = [&](int tile, int b) {
        const int k0 = tile * BK;
        float* asb = as + b*AS_W + tr*36 + th*16;
        #pragma unroll
        for (int ch = 0; ch < 4; ++ch) {
            int gk = k0 + th*16 + ch*4;
            int bytes = (grow < Nn && gk < Nn) ? 16 : 0;   // Nn%4==0: chunk all-or-none
            cp16pol(asb + ch*4, aRow + (gk < Nn-3 ? gk : Nn-4), bytes, pol);
        }
        float* xsb = xs + b*XS_W;
        cp16(xsb + xc*36 + xch*4, XT + xc*TST + k0 + xch*4);   // XT zero-padded to TST
        if (t < 8) cp16(xsb + 32*36 + t*4, XT + 32*TST + k0 + t*4);
    };

    unsigned long long acc[2][8];
    #pragma unroll
    for (int q = 0; q < 2; ++q)
        #pragma unroll
        for (int c = 0; c < 8; ++c) acc[q][c] = 0ull;
    unsigned long long a32[2] = {0ull, 0ull};

    load_tile(tS, 0);
    asm volatile("cp.async.commit_group;\n" ::: "memory");
    load_tile(tS + 1, 1);
    asm volatile("cp.async.commit_group;\n" ::: "memory");

    for (int i = tS; i < tE; ++i) {
        const int stage = (i - tS) % NSTAGE;
        if (i + 2 < tE) load_tile(i + 2, (i - tS + 2) % NSTAGE);
        asm volatile("cp.async.commit_group;\n" ::: "memory");
        asm volatile("cp.async.wait_group 2;\n" ::: "memory");
        __syncthreads();

        const float* aB = as + stage*AS_W + (rb + lane)*36;
        const float* xB = xs + stage*XS_W;
        #pragma unroll
        for (int s = 0; s < 8; ++s) {
            ulonglong2 a2[2];
            #pragma unroll
            for (int q = 0; q < 2; ++q)
                a2[q] = *reinterpret_cast<const ulonglong2*>(aB + q*(32*36) + s*4);
            #pragma unroll
            for (int cp = 0; cp < 4; ++cp) {
                ulonglong2 x0 = *reinterpret_cast<const ulonglong2*>(xB + (c0 + 2*cp    )*36 + s*4);
                ulonglong2 x1 = *reinterpret_cast<const ulonglong2*>(xB + (c0 + 2*cp + 1)*36 + s*4);
                #pragma unroll
                for (int q = 0; q < 2; ++q) {
                    ffma2(acc[q][2*cp    ], a2[q].x, x0.x);
                    ffma2(acc[q][2*cp    ], a2[q].y, x0.y);
                    ffma2(acc[q][2*cp + 1], a2[q].x, x1.x);
                    ffma2(acc[q][2*cp + 1], a2[q].y, x1.y);
                }
            }
            if (cg == 0) {
                ulonglong2 xv = *reinterpret_cast<const ulonglong2*>(xB + 32*36 + s*4);
                #pragma unroll
                for (int q = 0; q < 2; ++q) {
                    ffma2(a32[q], a2[q].x, xv.x);
                    ffma2(a32[q], a2[q].y, xv.y);
                }
            }
        }
        __syncthreads();
    }

    #pragma unroll
    for (int q = 0; q < 2; ++q) {
        int r = row0 + rb + 32*q + lane;
        if (r < Nn) {
            #pragma unroll
            for (int c = 0; c < 8; ++c)
                atomicAdd(YT + (c0 + c)*TST + r, sumb64(acc[q][c]));
            if (cg == 0) atomicAdd(YT + 32*TST + r, sumb64(a32[q]));
        }
    }
}

// ============================================================================
// Small kernels (transposed layout; unchanged from passing R3 kernel)
// ============================================================================
__global__ void init_k() {
    int tid = blockIdx.x * blockDim.x + threadIdx.x;
    int nth = gridDim.x * blockDim.x;
    for (int j = tid; j < NF*TST; j += nth) {
        g_X0T[j] = 0.f; g_X1T[j] = 0.f; g_X2T[j] = 0.f;
        g_C0T[j] = 0.f; g_C1T[j] = 0.f; g_C2T[j] = 0.f;
    }
    for (int j = tid; j < NU*TST; j += nth) { g_hT[j] = 0.f; g_uT[j] = 0.f; }
}

__global__ void build_enc(const float* __restrict__ inp, int tstep) {
    int tid = blockIdx.x * blockDim.x + threadIdx.x;
    int nth = gridDim.x * blockDim.x;
    for (int j = tid; j < NF*TST; j += nth) {
        int c = j / TST, n = j - c*TST;
        float v = 0.f;
        if (n < Nn) v = (c == 0) ? inp[n*TENC + tstep] : g_hT[(c-1)*TST + n];
        g_X0T[j] = v;
        g_X1T[j] = 0.f; g_X2T[j] = 0.f;
    }
}

__global__ void build_dec0() {
    int tid = blockIdx.x * blockDim.x + threadIdx.x;
    int nth = gridDim.x * blockDim.x;
    for (int j = tid; j < NF*TST; j += nth) {
        int c = j / TST, n = j - c*TST;
        float v = 0.f;
        if (n < Nn && c > 0) v = g_hT[(c-1)*TST + n];
        g_X0T[j] = v;
        g_X1T[j] = 0.f; g_X2T[j] = 0.f;
    }
}

__global__ void __launch_bounds__(256) gate_k(const float* __restrict__ W,
                                              const float* __restrict__ b) {
    __shared__ float sW[99*64];
    __shared__ float sx[99*32];
    const int t = threadIdx.x, lane = t & 31, w = t >> 5;
    const int rowb = blockIdx.x * 32;
    for (int j = t; j < 99*64; j += 256) sW[j] = W[j];
    for (int j = t; j < 99*32; j += 256) {
        int c = j >> 5, i = j & 31;
        const float* src = (c < 33) ? (g_X0T + c*TST)
                         : (c < 66) ? (g_X1T + (c-33)*TST)
                                    : (g_X2T + (c-66)*TST);
        sx[j] = src[rowb + i];
    }
    __syncthreads();

    float acc[8];
    #pragma unroll
    for (int cc = 0; cc < 8; ++cc) acc[cc] = b[8*w + cc];
    for (int k = 0; k < 99; ++k) {
        float xv = sx[k*32 + lane];
        const float4* wr = reinterpret_cast<const float4*>(sW + k*64 + 8*w);
        float4 w0 = wr[0], w1 = wr[1];
        acc[0] = fmaf(xv, w0.x, acc[0]); acc[1] = fmaf(xv, w0.y, acc[1]);
        acc[2] = fmaf(xv, w0.z, acc[2]); acc[3] = fmaf(xv, w0.w, acc[3]);
        acc[4] = fmaf(xv, w1.x, acc[4]); acc[5] = fmaf(xv, w1.y, acc[5]);
        acc[6] = fmaf(xv, w1.z, acc[6]); acc[7] = fmaf(xv, w1.w, acc[7]);
    }
    int row = rowb + lane;
    if (row < Nn) {
        #pragma unroll
        for (int cc = 0; cc < 8; ++cc) {
            int col = 8*w + cc;
            float s = 1.f / (1.f + expf(-acc[cc]));
            if (col < 32) g_C0T[(1 + col)*TST + row] = s * g_hT[col*TST + row];
            else          g_uT[(col - 32)*TST + row] = s;
        }
        if (w == 0) g_C0T[row] = g_X0T[row];
    }
    int tid = blockIdx.x * 256 + t, nth = gridDim.x * 256;
    for (int j = tid; j < NF*TST; j += nth) { g_C1T[j] = 0.f; g_C2T[j] = 0.f; }
}

__global__ void __launch_bounds__(256) cand_k(const float* __restrict__ W,
                                              const float* __restrict__ b) {
    __shared__ float sW[99*32];
    __shared__ float sx[99*32];
    const int t = threadIdx.x, lane = t & 31, w = t >> 5;
    const int rowb = blockIdx.x * 32;
    for (int j = t; j < 99*32; j += 256) sW[j] = W[j];
    for (int j = t; j < 99*32; j += 256) {
        int c = j >> 5, i = j & 31;
        const float* src = (c < 33) ? (g_C0T + c*TST)
                         : (c < 66) ? (g_C1T + (c-33)*TST)
                                    : (g_C2T + (c-66)*TST);
        sx[j] = src[rowb + i];
    }
    __syncthreads();

    float acc[4];
    #pragma unroll
    for (int cc = 0; cc < 4; ++cc) acc[cc] = b[4*w + cc];
    for (int k = 0; k < 99; ++k) {
        float xv = sx[k*32 + lane];
        float4 wv = *reinterpret_cast<const float4*>(sW + k*32 + 4*w);
        acc[0] = fmaf(xv, wv.x, acc[0]); acc[1] = fmaf(xv, wv.y, acc[1]);
        acc[2] = fmaf(xv, wv.z, acc[2]); acc[3] = fmaf(xv, wv.w, acc[3]);
    }
    int row = rowb + lane;
    if (row < Nn) {
        #pragma unroll
        for (int cc = 0; cc < 4; ++cc) {
            int col = 4*w + cc;
            float c = tanhf(acc[cc]);
            float u = g_uT[col*TST + row];
            float h = g_hT[col*TST + row];
            g_hT[col*TST + row] = u*h + (1.f - u)*c;
        }
    }
}

__global__ void __launch_bounds__(256) dec_post(const float* __restrict__ Wp,
                                                const float* __restrict__ bp,
                                                float* __restrict__ out, int tstep) {
    int tid = blockIdx.x * 256 + threadIdx.x;
    int nth = gridDim.x * 256;
    for (int row = tid; row < Nn; row += nth) {
        float acc = bp[0];
        #pragma unroll
        for (int c = 0; c < 32; ++c) acc = fmaf(g_hT[c*TST + row], Wp[c], acc);
        out[row*TDEC + tstep] = acc;
        g_X0T[row] = acc;
    }
    for (int j = tid; j < NU*TST; j += nth) g_X0T[TST + j] = g_hT[j];
    for (int j = tid; j < NF*TST; j += nth) { g_X1T[j] = 0.f; g_X2T[j] = 0.f; }
}

// ============================================================================
// Host launch sequence (graph-capturable: kernel launches only)
// ============================================================================
extern "C" void kernel_launch(void* const* d_in, const int* in_sizes, int n_in,
                              void* d_out, int out_size) {
    const float* inputs = (const float*)d_in[0];
    const float* adj    = (const float*)d_in[2];
    const float* enc_Wg = (const float*)d_in[3];
    const float* enc_bg = (const float*)d_in[4];
    const float* enc_Wc = (const float*)d_in[5];
    const float* enc_bc = (const float*)d_in[6];
    const float* dec_Wg = (const float*)d_in[7];
    const float* dec_bg = (const float*)d_in[8];
    const float* dec_Wc = (const float*)d_in[9];
    const float* dec_bc = (const float*)d_in[10];
    const float* dec_Wp = (const float*)d_in[11];
    const float* dec_bp = (const float*)d_in[12];
    float* out = (float*)d_out;

    cudaFuncSetAttribute(gemmT, cudaFuncAttributeMaxDynamicSharedMemorySize, GEMM_SMEM);
    cudaFuncSetAttribute(gemmT, cudaFuncAttributePreferredSharedMemoryCarveout, 100);

    init_k<<<256, 256>>>();

    for (int t = 0; t < TENC; ++t) {
        build_enc<<<256, 256>>>(inputs, t);
        gemmT<<<GGRID, 256, GEMM_SMEM>>>(adj, 0);
        gemmT<<<GGRID, 256, GEMM_SMEM>>>(adj, 1);
        gate_k<<<157, 256>>>(enc_Wg, enc_bg);
        gemmT<<<GGRID, 256, GEMM_SMEM>>>(adj, 2);
        gemmT<<<GGRID, 256, GEMM_SMEM>>>(adj, 3);
        cand_k<<<157, 256>>>(enc_Wc, enc_bc);
    }

    build_dec0<<<256, 256>>>();
    for (int t = 0; t < TDEC; ++t) {
        gemmT<<<GGRID, 256, GEMM_SMEM>>>(adj, 0);
        gemmT<<<GGRID, 256, GEMM_SMEM>>>(adj, 1);
        gate_k<<<157, 256>>>(dec_Wg, dec_bg);
        gemmT<<<GGRID, 256, GEMM_SMEM>>>(adj, 2);
        gemmT<<<GGRID, 256, GEMM_SMEM>>>(adj, 3);
        cand_k<<<157, 256>>>(dec_Wc, dec_bc);
        dec_post<<<157, 256>>>(dec_Wp, dec_bp, out, t);
    }
}

// round 6
// speedup vs baseline: 1.5001x; 1.5001x over previous
#include <cuda_runtime.h>
#include <cstdint>

#define Nn     5000
#define TST    5024
#define NF     33
#define NU     32
#define TENC   12
#define TDEC   12
#define MT     40            // M tiles of 128
#define SPLITK 7
#define GGRID  (MT*SPLITK)   // 280
#define KT     157           // K tiles of 32
#define BK     32
#define NSTG   3
#define AS_W   (128*36)      // 4608 words per A stage
#define BS_W   (40*36)       // 1440 words per B stage
#define DSMEM  (NSTG*(AS_W+BS_W)*4)   // 72576 bytes

// ---------------- persistent device state ----------------
__device__ float gA[25000000];                 // tf32-RN-rounded copy of adj
__device__ __align__(16) float g_X0T[NF*TST];
__device__ __align__(16) float g_X1T[NF*TST];
__device__ __align__(16) float g_X2T[NF*TST];
__device__ __align__(16) float g_C0T[NF*TST];
__device__ __align__(16) float g_C1T[NF*TST];
__device__ __align__(16) float g_C2T[NF*TST];
__device__ float g_hT[NU*TST];
__device__ float g_uT[NU*TST];

// ---------------- helpers ----------------
__device__ __forceinline__ void cp16z(void* dst, const void* src, int bytes) {
    unsigned s = (unsigned)__cvta_generic_to_shared(dst);
    asm volatile("cp.async.cg.shared.global [%0], [%1], 16, %2;\n"
                 :: "r"(s), "l"(src), "r"(bytes));
}
__device__ __forceinline__ float rna32(float x) {
    unsigned u;
    asm("cvt.rna.tf32.f32 %0, %1;" : "=r"(u) : "f"(x));
    return __uint_as_float(u);
}
__device__ __forceinline__ void mma16n8k8(float* c, unsigned a0, unsigned a1,
                                          unsigned a2, unsigned a3,
                                          unsigned b0, unsigned b1) {
    asm volatile("mma.sync.aligned.m16n8k8.row.col.f32.tf32.tf32.f32 "
                 "{%0,%1,%2,%3}, {%4,%5,%6,%7}, {%8,%9}, {%0,%1,%2,%3};"
                 : "+f"(c[0]), "+f"(c[1]), "+f"(c[2]), "+f"(c[3])
                 : "r"(a0), "r"(a1), "r"(a2), "r"(a3), "r"(b0), "r"(b1));
}
#define CP_COMMIT() asm volatile("cp.async.commit_group;" ::: "memory")
#define CP_WAIT2()  asm volatile("cp.async.wait_group 2;" ::: "memory")

// ============================================================================
// mma.sync tf32 GEMM: YT(f,r) += sum_k A(r,k) * XT(f,k)
// 128 rows/CTA, N=40 (33 used), K-tiles of 32, split-K=7, atomicAdd epilogue.
// Warp w: rows [16w,16w+16), all 5 N-tiles. Fragments loaded by scalar LDS
// from stride-36 tiles (conflict-free by construction).
// ============================================================================
__global__ void __launch_bounds__(256, 2) gemm_mma(int sel)
{
    const float* __restrict__ XT;
    float* __restrict__ YT;
    switch (sel) {
        case 0:  XT = g_X0T; YT = g_X1T; break;
        case 1:  XT = g_X1T; YT = g_X2T; break;
        case 2:  XT = g_C0T; YT = g_C1T; break;
        default: XT = g_C1T; YT = g_C2T; break;
    }

    extern __shared__ float sm[];
    float* as = sm;                 // [3][128][36]
    float* bs = sm + NSTG*AS_W;     // [3][40][36]

    const int t    = threadIdx.x;
    const int w    = t >> 5, lane = t & 31;
    const int r4   = lane >> 2, c4 = lane & 3;
    const int rt   = blockIdx.x % MT;
    const int ck   = blockIdx.x / MT;
    const int row0 = rt * 128;
    const int tS   = (KT * ck)       / SPLITK;
    const int tE   = (KT * (ck + 1)) / SPLITK;
    const int nt   = tE - tS;

    // zero B pad rows 33..39 (all stages; loader never writes them)
    for (int i = t; i < NSTG * 7 * BK; i += 256) {
        int s = i / (7 * BK), rem = i % (7 * BK);
        bs[s*BS_W + (33 + rem / BK) * 36 + (rem % BK)] = 0.f;
    }

    // A loader: thread -> row (t&127), k-half (t>>7)*16, 4 x 16B chunks
    const int tr = t & 127, th = t >> 7;
    const int grow = row0 + tr;
    const float* aRow = gA + (long)(grow < Nn ? grow : Nn - 1) * Nn;

    auto load_tile = [&](int tile, int s) {
        const int k0 = tile * BK;
        float* ad = as + s*AS_W + tr*36 + th*16;
        #pragma unroll
        for (int ch = 0; ch < 4; ++ch) {
            int gk = k0 + th*16 + ch*4;
            int bytes = (grow < Nn && gk < Nn) ? 16 : 0;
            cp16z(ad + ch*4, aRow + (gk < Nn - 3 ? gk : Nn - 4), bytes);
        }
        float* bd = bs + s*BS_W;
        #pragma unroll
        for (int j = 0; j < 2; ++j) {
            int c = j * 256 + t;
            if (c < 264) {                   // 33 rows x 8 chunks
                int row = c >> 3, ch = c & 7;
                cp16z(bd + row*36 + ch*4, XT + (long)row*TST + k0 + ch*4, 16);
            }
        }
    };

    float acc[5][4];
    #pragma unroll
    for (int ct = 0; ct < 5; ++ct)
        #pragma unroll
        for (int i = 0; i < 4; ++i) acc[ct][i] = 0.f;

    load_tile(tS, 0);
    CP_COMMIT();
    if (tS + 1 < tE) load_tile(tS + 1, 1);
    CP_COMMIT();

    for (int i = 0; i < nt; ++i) {
        const int stage = i % NSTG;
        if (i + 2 < nt) load_tile(tS + i + 2, (i + 2) % NSTG);
        CP_COMMIT();
        CP_WAIT2();
        __syncthreads();

        const float* aB = as + stage*AS_W + (w*16)*36;
        const float* bB = bs + stage*BS_W;
        #pragma unroll
        for (int ks = 0; ks < 4; ++ks) {
            const int kb = ks*8 + c4;
            unsigned a0 = __float_as_uint(aB[(r4    )*36 + kb    ]);
            unsigned a1 = __float_as_uint(aB[(r4 + 8)*36 + kb    ]);
            unsigned a2 = __float_as_uint(aB[(r4    )*36 + kb + 4]);
            unsigned a3 = __float_as_uint(aB[(r4 + 8)*36 + kb + 4]);
            #pragma unroll
            for (int ct = 0; ct < 5; ++ct) {
                unsigned b0 = __float_as_uint(bB[(ct*8 + r4)*36 + kb    ]);
                unsigned b1 = __float_as_uint(bB[(ct*8 + r4)*36 + kb + 4]);
                mma16n8k8(acc[ct], a0, a1, a2, a3, b0, b1);
            }
        }
        __syncthreads();
    }

    // epilogue: c0 (row=g, col=2*tig), c1 (+1), c2 (row=g+8), c3 (row=g+8,+1)
    const int rA = row0 + w*16 + r4;
    const int rB = rA + 8;
    #pragma unroll
    for (int ct = 0; ct < 5; ++ct) {
        const int col0 = ct*8 + 2*c4;
        const int col1 = col0 + 1;
        if (col0 < NF) {
            if (rA < Nn) atomicAdd(YT + (long)col0*TST + rA, acc[ct][0]);
            if (rB < Nn) atomicAdd(YT + (long)col0*TST + rB, acc[ct][2]);
        }
        if (col1 < NF) {
            if (rA < Nn) atomicAdd(YT + (long)col1*TST + rA, acc[ct][1]);
            if (rB < Nn) atomicAdd(YT + (long)col1*TST + rB, acc[ct][3]);
        }
    }
}

// ============================================================================
// Prep / elementwise kernels
// ============================================================================
__global__ void round_A(const float* __restrict__ A) {
    long i0 = (long)blockIdx.x * blockDim.x + threadIdx.x;
    long stride = (long)gridDim.x * blockDim.x;
    for (long i = i0; i < (long)Nn * Nn; i += stride) gA[i] = rna32(A[i]);
}

__global__ void roundX(int which) {
    float* B = which ? g_C1T : g_X1T;
    int i0 = blockIdx.x * blockDim.x + threadIdx.x;
    int nth = gridDim.x * blockDim.x;
    for (int i = i0; i < NF * TST; i += nth) B[i] = rna32(B[i]);
}

__global__ void init_k() {
    int tid = blockIdx.x * blockDim.x + threadIdx.x;
    int nth = gridDim.x * blockDim.x;
    for (int j = tid; j < NF * TST; j += nth) {
        g_X0T[j] = 0.f; g_X1T[j] = 0.f; g_X2T[j] = 0.f;
        g_C0T[j] = 0.f; g_C1T[j] = 0.f; g_C2T[j] = 0.f;
    }
    for (int j = tid; j < NU * TST; j += nth) { g_hT[j] = 0.f; g_uT[j] = 0.f; }
}

__global__ void build_enc(const float* __restrict__ inp, int tstep) {
    int tid = blockIdx.x * blockDim.x + threadIdx.x;
    int nth = gridDim.x * blockDim.x;
    for (int j = tid; j < NF * TST; j += nth) {
        int c = j / TST, n = j - c * TST;
        float v = 0.f;
        if (n < Nn) v = (c == 0) ? inp[n * TENC + tstep] : g_hT[(c - 1) * TST + n];
        g_X0T[j] = rna32(v);
        g_X1T[j] = 0.f; g_X2T[j] = 0.f;
    }
}

__global__ void build_dec0() {
    int tid = blockIdx.x * blockDim.x + threadIdx.x;
    int nth = gridDim.x * blockDim.x;
    for (int j = tid; j < NF * TST; j += nth) {
        int c = j / TST, n = j - c * TST;
        float v = 0.f;
        if (n < Nn && c > 0) v = g_hT[(c - 1) * TST + n];
        g_X0T[j] = rna32(v);
        g_X1T[j] = 0.f; g_X2T[j] = 0.f;
    }
}

__global__ void __launch_bounds__(256) gate_k(const float* __restrict__ W,
                                              const float* __restrict__ b) {
    __shared__ float sW[99 * 64];
    __shared__ float sx[99 * 32];
    const int t = threadIdx.x, lane = t & 31, w = t >> 5;
    const int rowb = blockIdx.x * 32;
    for (int j = t; j < 99 * 64; j += 256) sW[j] = W[j];
    for (int j = t; j < 99 * 32; j += 256) {
        int c = j >> 5, i = j & 31;
        const float* src = (c < 33) ? (g_X0T + c * TST)
                         : (c < 66) ? (g_X1T + (c - 33) * TST)
                                    : (g_X2T + (c - 66) * TST);
        sx[j] = src[rowb + i];
    }
    __syncthreads();

    float acc[8];
    #pragma unroll
    for (int cc = 0; cc < 8; ++cc) acc[cc] = b[8 * w + cc];
    for (int k = 0; k < 99; ++k) {
        float xv = sx[k * 32 + lane];
        const float4* wr = reinterpret_cast<const float4*>(sW + k * 64 + 8 * w);
        float4 w0 = wr[0], w1 = wr[1];
        acc[0] = fmaf(xv, w0.x, acc[0]); acc[1] = fmaf(xv, w0.y, acc[1]);
        acc[2] = fmaf(xv, w0.z, acc[2]); acc[3] = fmaf(xv, w0.w, acc[3]);
        acc[4] = fmaf(xv, w1.x, acc[4]); acc[5] = fmaf(xv, w1.y, acc[5]);
        acc[6] = fmaf(xv, w1.z, acc[6]); acc[7] = fmaf(xv, w1.w, acc[7]);
    }
    int row = rowb + lane;
    if (row < Nn) {
        #pragma unroll
        for (int cc = 0; cc < 8; ++cc) {
            int col = 8 * w + cc;
            float s = 1.f / (1.f + expf(-acc[cc]));
            if (col < 32) g_C0T[(1 + col) * TST + row] = rna32(s * g_hT[col * TST + row]);
            else          g_uT[(col - 32) * TST + row] = s;
        }
        if (w == 0) g_C0T[row] = g_X0T[row];   // already rounded
    }
    int tid = blockIdx.x * 256 + t, nth = gridDim.x * 256;
    for (int j = tid; j < NF * TST; j += nth) { g_C1T[j] = 0.f; g_C2T[j] = 0.f; }
}

__global__ void __launch_bounds__(256) cand_k(const float* __restrict__ W,
                                              const float* __restrict__ b) {
    __shared__ float sW[99 * 32];
    __shared__ float sx[99 * 32];
    const int t = threadIdx.x, lane = t & 31, w = t >> 5;
    const int rowb = blockIdx.x * 32;
    for (int j = t; j < 99 * 32; j += 256) sW[j] = W[j];
    for (int j = t; j < 99 * 32; j += 256) {
        int c = j >> 5, i = j & 31;
        const float* src = (c < 33) ? (g_C0T + c * TST)
                         : (c < 66) ? (g_C1T + (c - 33) * TST)
                                    : (g_C2T + (c - 66) * TST);
        sx[j] = src[rowb + i];
    }
    __syncthreads();

    float acc[4];
    #pragma unroll
    for (int cc = 0; cc < 4; ++cc) acc[cc] = b[4 * w + cc];
    for (int k = 0; k < 99; ++k) {
        float xv = sx[k * 32 + lane];
        float4 wv = *reinterpret_cast<const float4*>(sW + k * 32 + 4 * w);
        acc[0] = fmaf(xv, wv.x, acc[0]); acc[1] = fmaf(xv, wv.y, acc[1]);
        acc[2] = fmaf(xv, wv.z, acc[2]); acc[3] = fmaf(xv, wv.w, acc[3]);
    }
    int row = rowb + lane;
    if (row < Nn) {
        #pragma unroll
        for (int cc = 0; cc < 4; ++cc) {
            int col = 4 * w + cc;
            float c = tanhf(acc[cc]);
            float u = g_uT[col * TST + row];
            float h = g_hT[col * TST + row];
            g_hT[col * TST + row] = u * h + (1.f - u) * c;
        }
    }
}

__global__ void __launch_bounds__(256) dec_post(const float* __restrict__ Wp,
                                                const float* __restrict__ bp,
                                                float* __restrict__ out, int tstep) {
    int tid = blockIdx.x * 256 + threadIdx.x;
    int nth = gridDim.x * 256;
    for (int row = tid; row < Nn; row += nth) {
        float acc = bp[0];
        #pragma unroll
        for (int c = 0; c < 32; ++c) acc = fmaf(g_hT[c * TST + row], Wp[c], acc);
        out[row * TDEC + tstep] = acc;
        g_X0T[row] = rna32(acc);
    }
    for (int j = tid; j < NU * TST; j += nth) g_X0T[TST + j] = rna32(g_hT[j]);
    for (int j = tid; j < NF * TST; j += nth) { g_X1T[j] = 0.f; g_X2T[j] = 0.f; }
}

// ============================================================================
// Host launch sequence
// ============================================================================
extern "C" void kernel_launch(void* const* d_in, const int* in_sizes, int n_in,
                              void* d_out, int out_size) {
    const float* inputs = (const float*)d_in[0];
    const float* adj    = (const float*)d_in[2];
    const float* enc_Wg = (const float*)d_in[3];
    const float* enc_bg = (const float*)d_in[4];
    const float* enc_Wc = (const float*)d_in[5];
    const float* enc_bc = (const float*)d_in[6];
    const float* dec_Wg = (const float*)d_in[7];
    const float* dec_bg = (const float*)d_in[8];
    const float* dec_Wc = (const float*)d_in[9];
    const float* dec_bc = (const float*)d_in[10];
    const float* dec_Wp = (const float*)d_in[11];
    const float* dec_bp = (const float*)d_in[12];
    float* out = (float*)d_out;

    cudaFuncSetAttribute(gemm_mma, cudaFuncAttributeMaxDynamicSharedMemorySize, DSMEM);
    cudaFuncSetAttribute(gemm_mma, cudaFuncAttributePreferredSharedMemoryCarveout, 100);

    round_A<<<1024, 256>>>(adj);
    init_k<<<256, 256>>>();

    for (int t = 0; t < TENC; ++t) {
        build_enc<<<256, 256>>>(inputs, t);
        gemm_mma<<<GGRID, 256, DSMEM>>>(0);
        roundX<<<128, 256>>>(0);
        gemm_mma<<<GGRID, 256, DSMEM>>>(1);
        gate_k<<<157, 256>>>(enc_Wg, enc_bg);
        gemm_mma<<<GGRID, 256, DSMEM>>>(2);
        roundX<<<128, 256>>>(1);
        gemm_mma<<<GGRID, 256, DSMEM>>>(3);
        cand_k<<<157, 256>>>(enc_Wc, enc_bc);
    }

    build_dec0<<<256, 256>>>();
    for (int t = 0; t < TDEC; ++t) {
        gemm_mma<<<GGRID, 256, DSMEM>>>(0);
        roundX<<<128, 256>>>(0);
        gemm_mma<<<GGRID, 256, DSMEM>>>(1);
        gate_k<<<157, 256>>>(dec_Wg, dec_bg);
        gemm_mma<<<GGRID, 256, DSMEM>>>(2);
        roundX<<<128, 256>>>(1);
        gemm_mma<<<GGRID, 256, DSMEM>>>(3);
        cand_k<<<157, 256>>>(dec_Wc, dec_bc);
        dec_post<<<157, 256>>>(dec_Wp, dec_bp, out, t);
    }
}

// round 7
// speedup vs baseline: 1.6045x; 1.0696x over previous
#include <cuda_runtime.h>
#include <cstdint>

#define Nn     5000
#define TST    5024
#define NF     33
#define NU     32
#define TENC   12
#define TDEC   12
#define BM     64
#define MT     79            // ceil(5000/64)
#define SPLITK 5
#define GGRID  (MT*SPLITK)   // 395
#define KT     157           // K tiles of 32
#define BK     32
#define NSTG   5
#define AS_W   (BM*36)       // 2304 words per A stage
#define BS_W   (40*36)       // 1440 words per B stage
#define DSMEM  (NSTG*(AS_W+BS_W)*4)   // 74880 bytes

// ---------------- persistent device state ----------------
__device__ float gA[25000000];                 // tf32-RN-rounded copy of adj
__device__ __align__(16) float g_X0T[NF*TST];
__device__ __align__(16) float g_X1T[NF*TST];
__device__ __align__(16) float g_X2T[NF*TST];
__device__ __align__(16) float g_C0T[NF*TST];
__device__ __align__(16) float g_C1T[NF*TST];
__device__ __align__(16) float g_C2T[NF*TST];
__device__ float g_hT[NU*TST];
__device__ float g_uT[NU*TST];

// ---------------- helpers ----------------
__device__ __forceinline__ void cp16z(void* dst, const void* src, int bytes) {
    unsigned s = (unsigned)__cvta_generic_to_shared(dst);
    asm volatile("cp.async.cg.shared.global [%0], [%1], 16, %2;\n"
                 :: "r"(s), "l"(src), "r"(bytes));
}
__device__ __forceinline__ float rna32(float x) {
    unsigned u;
    asm("cvt.rna.tf32.f32 %0, %1;" : "=r"(u) : "f"(x));
    return __uint_as_float(u);
}
__device__ __forceinline__ void mma16n8k8(float* c, unsigned a0, unsigned a1,
                                          unsigned a2, unsigned a3,
                                          unsigned b0, unsigned b1) {
    asm volatile("mma.sync.aligned.m16n8k8.row.col.f32.tf32.tf32.f32 "
                 "{%0,%1,%2,%3}, {%4,%5,%6,%7}, {%8,%9}, {%0,%1,%2,%3};"
                 : "+f"(c[0]), "+f"(c[1]), "+f"(c[2]), "+f"(c[3])
                 : "r"(a0), "r"(a1), "r"(a2), "r"(a3), "r"(b0), "r"(b1));
}
#define CP_COMMIT() asm volatile("cp.async.commit_group;" ::: "memory")
#define CP_WAIT3()  asm volatile("cp.async.wait_group 3;" ::: "memory")

// ============================================================================
// mma.sync tf32 GEMM: YT(f,r) += sum_k A(r,k) * XT(f,k)
// 64 rows/CTA (4 warps x 16 rows), N=40 (33 used), K-tiles of 32, split-K=5.
// 5-stage cp.async ring, depth-4 lookahead, one barrier per iteration.
// ============================================================================
__global__ void __launch_bounds__(128, 3) gemm_mma(int sel)
{
    const float* __restrict__ XT;
    float* __restrict__ YT;
    switch (sel) {
        case 0:  XT = g_X0T; YT = g_X1T; break;
        case 1:  XT = g_X1T; YT = g_X2T; break;
        case 2:  XT = g_C0T; YT = g_C1T; break;
        default: XT = g_C1T; YT = g_C2T; break;
    }

    extern __shared__ float sm[];
    float* as = sm;                 // [5][64][36]
    float* bs = sm + NSTG*AS_W;     // [5][40][36]

    const int t    = threadIdx.x;
    const int w    = t >> 5, lane = t & 31;
    const int r4   = lane >> 2, c4 = lane & 3;
    const int rt   = blockIdx.x % MT;
    const int ck   = blockIdx.x / MT;
    const int row0 = rt * BM;
    const int tS   = (KT * ck)       / SPLITK;
    const int tE   = (KT * (ck + 1)) / SPLITK;
    const int nt   = tE - tS;

    // zero B pad rows 33..39 in all stages (loader never writes them)
    for (int i = t; i < NSTG * 7 * BK; i += 128) {
        int s = i / (7 * BK), rem = i % (7 * BK);
        bs[s*BS_W + (33 + rem / BK) * 36 + (rem % BK)] = 0.f;
    }

    // A loader: thread -> row (t>>1), k-half (t&1)*16, 4 x 16B chunks
    const int tr = t >> 1, th = t & 1;
    const int grow = row0 + tr;
    const float* aRow = gA + (long)(grow < Nn ? grow : Nn - 1) * Nn;

    auto load_tile = [&](int tile, int s) {
        const int k0 = tile * BK;
        float* ad = as + s*AS_W + tr*36 + th*16;
        #pragma unroll
        for (int ch = 0; ch < 4; ++ch) {
            int gk = k0 + th*16 + ch*4;
            int bytes = (grow < Nn && gk < Nn) ? 16 : 0;
            cp16z(ad + ch*4, aRow + (gk < Nn - 3 ? gk : Nn - 4), bytes);
        }
        float* bd = bs + s*BS_W;
        #pragma unroll
        for (int j = 0; j < 3; ++j) {
            int c = j * 128 + t;
            if (c < 264) {                   // 33 rows x 8 chunks
                int row = c >> 3, ch = c & 7;
                cp16z(bd + row*36 + ch*4, XT + (long)row*TST + k0 + ch*4, 16);
            }
        }
    };

    float acc[5][4];
    #pragma unroll
    for (int ct = 0; ct < 5; ++ct)
        #pragma unroll
        for (int i = 0; i < 4; ++i) acc[ct][i] = 0.f;

    // prologue: 4 tiles in flight
    #pragma unroll
    for (int p = 0; p < 4; ++p) {
        if (p < nt) load_tile(tS + p, p);
        CP_COMMIT();
    }

    for (int i = 0; i < nt; ++i) {
        CP_WAIT3();                 // tile i complete
        __syncthreads();            // all warps done with iter i-1 compute
        if (i + 4 < nt) load_tile(tS + i + 4, (i + 4) % NSTG);
        CP_COMMIT();

        const int stage = i % NSTG;
        const float* aB = as + stage*AS_W + (w*16)*36;
        const float* bB = bs + stage*BS_W;
        #pragma unroll
        for (int ks = 0; ks < 4; ++ks) {
            const int kb = ks*8 + c4;
            unsigned a0 = __float_as_uint(aB[(r4    )*36 + kb    ]);
            unsigned a1 = __float_as_uint(aB[(r4 + 8)*36 + kb    ]);
            unsigned a2 = __float_as_uint(aB[(r4    )*36 + kb + 4]);
            unsigned a3 = __float_as_uint(aB[(r4 + 8)*36 + kb + 4]);
            #pragma unroll
            for (int ct = 0; ct < 5; ++ct) {
                unsigned b0 = __float_as_uint(bB[(ct*8 + r4)*36 + kb    ]);
                unsigned b1 = __float_as_uint(bB[(ct*8 + r4)*36 + kb + 4]);
                mma16n8k8(acc[ct], a0, a1, a2, a3, b0, b1);
            }
        }
    }

    const int rA = row0 + w*16 + r4;
    const int rB = rA + 8;
    #pragma unroll
    for (int ct = 0; ct < 5; ++ct) {
        const int col0 = ct*8 + 2*c4;
        const int col1 = col0 + 1;
        if (col0 < NF) {
            if (rA < Nn) atomicAdd(YT + (long)col0*TST + rA, acc[ct][0]);
            if (rB < Nn) atomicAdd(YT + (long)col0*TST + rB, acc[ct][2]);
        }
        if (col1 < NF) {
            if (rA < Nn) atomicAdd(YT + (long)col1*TST + rA, acc[ct][1]);
            if (rB < Nn) atomicAdd(YT + (long)col1*TST + rB, acc[ct][3]);
        }
    }
}

// ============================================================================
// Prep / elementwise kernels
// ============================================================================
__global__ void round_A(const float* __restrict__ A) {
    long i0 = (long)blockIdx.x * blockDim.x + threadIdx.x;
    long stride = (long)gridDim.x * blockDim.x;
    for (long i = i0; i < (long)Nn * Nn; i += stride) gA[i] = rna32(A[i]);
}

__global__ void roundX(int which) {
    float* B = which ? g_C1T : g_X1T;
    int i0 = blockIdx.x * blockDim.x + threadIdx.x;
    int nth = gridDim.x * blockDim.x;
    for (int i = i0; i < NF * TST; i += nth) B[i] = rna32(B[i]);
}

__global__ void init_k() {
    int tid = blockIdx.x * blockDim.x + threadIdx.x;
    int nth = gridDim.x * blockDim.x;
    for (int j = tid; j < NF * TST; j += nth) {
        g_X0T[j] = 0.f; g_X1T[j] = 0.f; g_X2T[j] = 0.f;
        g_C0T[j] = 0.f; g_C1T[j] = 0.f; g_C2T[j] = 0.f;
    }
    for (int j = tid; j < NU * TST; j += nth) { g_hT[j] = 0.f; g_uT[j] = 0.f; }
}

__global__ void build_enc(const float* __restrict__ inp, int tstep) {
    int tid = blockIdx.x * blockDim.x + threadIdx.x;
    int nth = gridDim.x * blockDim.x;
    for (int j = tid; j < NF * TST; j += nth) {
        int c = j / TST, n = j - c * TST;
        float v = 0.f;
        if (n < Nn) v = (c == 0) ? inp[n * TENC + tstep] : g_hT[(c - 1) * TST + n];
        g_X0T[j] = rna32(v);
        g_X1T[j] = 0.f; g_X2T[j] = 0.f;
    }
}

__global__ void build_dec0() {
    int tid = blockIdx.x * blockDim.x + threadIdx.x;
    int nth = gridDim.x * blockDim.x;
    for (int j = tid; j < NF * TST; j += nth) {
        int c = j / TST, n = j - c * TST;
        float v = 0.f;
        if (n < Nn && c > 0) v = g_hT[(c - 1) * TST + n];
        g_X0T[j] = rna32(v);
        g_X1T[j] = 0.f; g_X2T[j] = 0.f;
    }
}

__global__ void __launch_bounds__(256) gate_k(const float* __restrict__ W,
                                              const float* __restrict__ b) {
    __shared__ float sW[99 * 64];
    __shared__ float sx[99 * 32];
    const int t = threadIdx.x, lane = t & 31, w = t >> 5;
    const int rowb = blockIdx.x * 32;
    for (int j = t; j < 99 * 64; j += 256) sW[j] = W[j];
    for (int j = t; j < 99 * 32; j += 256) {
        int c = j >> 5, i = j & 31;
        const float* src = (c < 33) ? (g_X0T + c * TST)
                         : (c < 66) ? (g_X1T + (c - 33) * TST)
                                    : (g_X2T + (c - 66) * TST);
        sx[j] = src[rowb + i];
    }
    __syncthreads();

    float acc[8];
    #pragma unroll
    for (int cc = 0; cc < 8; ++cc) acc[cc] = b[8 * w + cc];
    for (int k = 0; k < 99; ++k) {
        float xv = sx[k * 32 + lane];
        const float4* wr = reinterpret_cast<const float4*>(sW + k * 64 + 8 * w);
        float4 w0 = wr[0], w1 = wr[1];
        acc[0] = fmaf(xv, w0.x, acc[0]); acc[1] = fmaf(xv, w0.y, acc[1]);
        acc[2] = fmaf(xv, w0.z, acc[2]); acc[3] = fmaf(xv, w0.w, acc[3]);
        acc[4] = fmaf(xv, w1.x, acc[4]); acc[5] = fmaf(xv, w1.y, acc[5]);
        acc[6] = fmaf(xv, w1.z, acc[6]); acc[7] = fmaf(xv, w1.w, acc[7]);
    }
    int row = rowb + lane;
    if (row < Nn) {
        #pragma unroll
        for (int cc = 0; cc < 8; ++cc) {
            int col = 8 * w + cc;
            float s = 1.f / (1.f + expf(-acc[cc]));
            if (col < 32) g_C0T[(1 + col) * TST + row] = rna32(s * g_hT[col * TST + row]);
            else          g_uT[(col - 32) * TST + row] = s;
        }
        if (w == 0) g_C0T[row] = g_X0T[row];   // already rounded
    }
    int tid = blockIdx.x * 256 + t, nth = gridDim.x * 256;
    for (int j = tid; j < NF * TST; j += nth) { g_C1T[j] = 0.f; g_C2T[j] = 0.f; }
}

__global__ void __launch_bounds__(256) cand_k(const float* __restrict__ W,
                                              const float* __restrict__ b) {
    __shared__ float sW[99 * 32];
    __shared__ float sx[99 * 32];
    const int t = threadIdx.x, lane = t & 31, w = t >> 5;
    const int rowb = blockIdx.x * 32;
    for (int j = t; j < 99 * 32; j += 256) sW[j] = W[j];
    for (int j = t; j < 99 * 32; j += 256) {
        int c = j >> 5, i = j & 31;
        const float* src = (c < 33) ? (g_C0T + c * TST)
                         : (c < 66) ? (g_C1T + (c - 33) * TST)
                                    : (g_C2T + (c - 66) * TST);
        sx[j] = src[rowb + i];
    }
    __syncthreads();

    float acc[4];
    #pragma unroll
    for (int cc = 0; cc < 4; ++cc) acc[cc] = b[4 * w + cc];
    for (int k = 0; k < 99; ++k) {
        float xv = sx[k * 32 + lane];
        float4 wv = *reinterpret_cast<const float4*>(sW + k * 32 + 4 * w);
        acc[0] = fmaf(xv, wv.x, acc[0]); acc[1] = fmaf(xv, wv.y, acc[1]);
        acc[2] = fmaf(xv, wv.z, acc[2]); acc[3] = fmaf(xv, wv.w, acc[3]);
    }
    int row = rowb + lane;
    if (row < Nn) {
        #pragma unroll
        for (int cc = 0; cc < 4; ++cc) {
            int col = 4 * w + cc;
            float c = tanhf(acc[cc]);
            float u = g_uT[col * TST + row];
            float h = g_hT[col * TST + row];
            g_hT[col * TST + row] = u * h + (1.f - u) * c;
        }
    }
}

__global__ void __launch_bounds__(256) dec_post(const float* __restrict__ Wp,
                                                const float* __restrict__ bp,
                                                float* __restrict__ out, int tstep) {
    int tid = blockIdx.x * 256 + threadIdx.x;
    int nth = gridDim.x * 256;
    for (int row = tid; row < Nn; row += nth) {
        float acc = bp[0];
        #pragma unroll
        for (int c = 0; c < 32; ++c) acc = fmaf(g_hT[c * TST + row], Wp[c], acc);
        out[row * TDEC + tstep] = acc;
        g_X0T[row] = rna32(acc);
    }
    for (int j = tid; j < NU * TST; j += nth) g_X0T[TST + j] = rna32(g_hT[j]);
    for (int j = tid; j < NF * TST; j += nth) { g_X1T[j] = 0.f; g_X2T[j] = 0.f; }
}

// ============================================================================
// Host launch sequence
// ============================================================================
extern "C" void kernel_launch(void* const* d_in, const int* in_sizes, int n_in,
                              void* d_out, int out_size) {
    const float* inputs = (const float*)d_in[0];
    const float* adj    = (const float*)d_in[2];
    const float* enc_Wg = (const float*)d_in[3];
    const float* enc_bg = (const float*)d_in[4];
    const float* enc_Wc = (const float*)d_in[5];
    const float* enc_bc = (const float*)d_in[6];
    const float* dec_Wg = (const float*)d_in[7];
    const float* dec_bg = (const float*)d_in[8];
    const float* dec_Wc = (const float*)d_in[9];
    const float* dec_bc = (const float*)d_in[10];
    const float* dec_Wp = (const float*)d_in[11];
    const float* dec_bp = (const float*)d_in[12];
    float* out = (float*)d_out;

    cudaFuncSetAttribute(gemm_mma, cudaFuncAttributeMaxDynamicSharedMemorySize, DSMEM);
    cudaFuncSetAttribute(gemm_mma, cudaFuncAttributePreferredSharedMemoryCarveout, 100);

    round_A<<<1024, 256>>>(adj);
    init_k<<<256, 256>>>();

    for (int t = 0; t < TENC; ++t) {
        build_enc<<<256, 256>>>(inputs, t);
        gemm_mma<<<GGRID, 128, DSMEM>>>(0);
        roundX<<<128, 256>>>(0);
        gemm_mma<<<GGRID, 128, DSMEM>>>(1);
        gate_k<<<157, 256>>>(enc_Wg, enc_bg);
        gemm_mma<<<GGRID, 128, DSMEM>>>(2);
        roundX<<<128, 256>>>(1);
        gemm_mma<<<GGRID, 128, DSMEM>>>(3);
        cand_k<<<157, 256>>>(enc_Wc, enc_bc);
    }

    build_dec0<<<256, 256>>>();
    for (int t = 0; t < TDEC; ++t) {
        gemm_mma<<<GGRID, 128, DSMEM>>>(0);
        roundX<<<128, 256>>>(0);
        gemm_mma<<<GGRID, 128, DSMEM>>>(1);
        gate_k<<<157, 256>>>(dec_Wg, dec_bg);
        gemm_mma<<<GGRID, 128, DSMEM>>>(2);
        roundX<<<128, 256>>>(1);
        gemm_mma<<<GGRID, 128, DSMEM>>>(3);
        cand_k<<<157, 256>>>(dec_Wc, dec_bc);
        dec_post<<<157, 256>>>(dec_Wp, dec_bp, out, t);
    }
}

// round 8
// speedup vs baseline: 2.7660x; 1.7239x over previous
#include <cuda_runtime.h>
#include <cuda_fp16.h>
#include <cstdint>

#define Nn     5000
#define TST    5024          // fp32 buffer node stride
#define TSTH   5056          // fp16 buffer node stride (79*64)
#define NF     33
#define NU     32
#define TENC   12
#define TDEC   12
#define BM     64
#define MT     79            // ceil(5000/64)
#define SPLITK 5
#define GGRID  (MT*SPLITK)   // 395
#define KT     79            // K tiles of 64
#define BK     64
#define NSTG   5
#define LDH    72            // fp16 smem row stride (64 + 8 pad)
#define ASH_W  (BM*LDH)      // 4608 halfs / stage
#define BSH_W  (40*LDH)      // 2880 halfs / stage
#define DSMEM  (NSTG*(ASH_W+BSH_W)*2)   // 74880 bytes

// ---------------- persistent device state ----------------
__device__ __half gAh[25000000];               // fp16 copy of adj (50MB)
// fp32 masters (consumed by gate/cand/dec_post)
__device__ __align__(16) float g_X0T[NF*TST];
__device__ __align__(16) float g_X1T[NF*TST];
__device__ __align__(16) float g_X2T[NF*TST];
__device__ __align__(16) float g_C0T[NF*TST];
__device__ __align__(16) float g_C1T[NF*TST];
__device__ __align__(16) float g_C2T[NF*TST];
// fp16 shadows (GEMM B operands), zero-padded to TSTH
__device__ __align__(16) __half g_X0h[NF*TSTH];
__device__ __align__(16) __half g_X1h[NF*TSTH];
__device__ __align__(16) __half g_C0h[NF*TSTH];
__device__ __align__(16) __half g_C1h[NF*TSTH];
__device__ float g_hT[NU*TST];
__device__ float g_uT[NU*TST];

// ---------------- helpers ----------------
__device__ __forceinline__ void cp16z(void* dst, const void* src, int bytes) {
    unsigned s = (unsigned)__cvta_generic_to_shared(dst);
    asm volatile("cp.async.cg.shared.global [%0], [%1], 16, %2;\n"
                 :: "r"(s), "l"(src), "r"(bytes));
}
__device__ __forceinline__ void mma_f16(float* c, unsigned a0, unsigned a1,
                                        unsigned a2, unsigned a3,
                                        unsigned b0, unsigned b1) {
    asm volatile("mma.sync.aligned.m16n8k16.row.col.f32.f16.f16.f32 "
                 "{%0,%1,%2,%3}, {%4,%5,%6,%7}, {%8,%9}, {%0,%1,%2,%3};"
                 : "+f"(c[0]), "+f"(c[1]), "+f"(c[2]), "+f"(c[3])
                 : "r"(a0), "r"(a1), "r"(a2), "r"(a3), "r"(b0), "r"(b1));
}
#define CP_COMMIT() asm volatile("cp.async.commit_group;" ::: "memory")
#define CP_WAIT3()  asm volatile("cp.async.wait_group 3;" ::: "memory")

// ============================================================================
// fp16 mma GEMM: YT(f,r) += sum_k A(r,k) * Xh(f,k)
// 64 rows/CTA (4 warps x 16 rows), N=40 (33 used), K-tiles of 64, split-K=5.
// 5-stage cp.async ring, depth-4 lookahead, one barrier per iteration.
// ============================================================================
__global__ void __launch_bounds__(128, 3) gemm_mma(int sel)
{
    const __half* __restrict__ XH;
    float* __restrict__ YT;
    switch (sel) {
        case 0:  XH = g_X0h; YT = g_X1T; break;
        case 1:  XH = g_X1h; YT = g_X2T; break;
        case 2:  XH = g_C0h; YT = g_C1T; break;
        default: XH = g_C1h; YT = g_C2T; break;
    }

    extern __shared__ __half smh[];
    __half* as = smh;                  // [5][64][72]
    __half* bs = smh + NSTG*ASH_W;     // [5][40][72]

    const int t    = threadIdx.x;
    const int w    = t >> 5, lane = t & 31;
    const int r4   = lane >> 2, c4 = lane & 3;
    const int rt   = blockIdx.x % MT;
    const int ck   = blockIdx.x / MT;
    const int row0 = rt * BM;
    const int tS   = (KT * ck)       / SPLITK;
    const int tE   = (KT * (ck + 1)) / SPLITK;
    const int nt   = tE - tS;

    // zero B pad rows 33..39 in all stages (loader never writes them)
    for (int i = t; i < NSTG * 7 * BK; i += 128) {
        int s = i / (7 * BK), rem = i % (7 * BK);
        bs[s*BSH_W + (33 + rem / BK) * LDH + (rem % BK)] = __half(0.f);
    }

    // A loader: thread -> row (t>>1), half (t&1)*32 halfs, 4 x 16B chunks
    const int tr = t >> 1, th = t & 1;
    const int grow = row0 + tr;
    const __half* aRow = gAh + (long)(grow < Nn ? grow : Nn - 1) * Nn;

    auto load_tile = [&](int tile, int s) {
        const int k0 = tile * BK;
        __half* ad = as + s*ASH_W + tr*LDH + th*32;
        #pragma unroll
        for (int ch = 0; ch < 4; ++ch) {
            int gk = k0 + th*32 + ch*8;                     // 8 halfs = 16B
            int bytes = (grow < Nn && gk + 8 <= Nn) ? 16 : 0;
            cp16z(ad + ch*8, aRow + (gk + 8 <= Nn ? gk : Nn - 8), bytes);
        }
        __half* bd = bs + s*BSH_W;
        #pragma unroll
        for (int j = 0; j < 3; ++j) {
            int c = j * 128 + t;
            if (c < 264) {                                  // 33 rows x 8 chunks
                int row = c >> 3, ch = c & 7;
                cp16z(bd + row*LDH + ch*8, XH + (long)row*TSTH + k0 + ch*8, 16);
            }
        }
    };

    float acc[5][4];
    #pragma unroll
    for (int ct = 0; ct < 5; ++ct)
        #pragma unroll
        for (int i = 0; i < 4; ++i) acc[ct][i] = 0.f;

    #pragma unroll
    for (int p = 0; p < 4; ++p) {
        if (p < nt) load_tile(tS + p, p);
        CP_COMMIT();
    }

    for (int i = 0; i < nt; ++i) {
        CP_WAIT3();
        __syncthreads();
        if (i + 4 < nt) load_tile(tS + i + 4, (i + 4) % NSTG);
        CP_COMMIT();

        const int stage = i % NSTG;
        const __half* aB = as + stage*ASH_W + (w*16)*LDH;
        const __half* bB = bs + stage*BSH_W;
        #pragma unroll
        for (int ks = 0; ks < 4; ++ks) {
            const int kb = ks*16 + 2*c4;
            unsigned a0 = *(const unsigned*)(aB + (r4    )*LDH + kb    );
            unsigned a1 = *(const unsigned*)(aB + (r4 + 8)*LDH + kb    );
            unsigned a2 = *(const unsigned*)(aB + (r4    )*LDH + kb + 8);
            unsigned a3 = *(const unsigned*)(aB + (r4 + 8)*LDH + kb + 8);
            #pragma unroll
            for (int ct = 0; ct < 5; ++ct) {
                unsigned b0 = *(const unsigned*)(bB + (ct*8 + r4)*LDH + kb    );
                unsigned b1 = *(const unsigned*)(bB + (ct*8 + r4)*LDH + kb + 8);
                mma_f16(acc[ct], a0, a1, a2, a3, b0, b1);
            }
        }
    }

    const int rA = row0 + w*16 + r4;
    const int rB = rA + 8;
    #pragma unroll
    for (int ct = 0; ct < 5; ++ct) {
        const int col0 = ct*8 + 2*c4;
        const int col1 = col0 + 1;
        if (col0 < NF) {
            if (rA < Nn) atomicAdd(YT + (long)col0*TST + rA, acc[ct][0]);
            if (rB < Nn) atomicAdd(YT + (long)col0*TST + rB, acc[ct][2]);
        }
        if (col1 < NF) {
            if (rA < Nn) atomicAdd(YT + (long)col1*TST + rA, acc[ct][1]);
            if (rB < Nn) atomicAdd(YT + (long)col1*TST + rB, acc[ct][3]);
        }
    }
}

// ============================================================================
// Prep / elementwise kernels
// ============================================================================
__global__ void conv_A(const float* __restrict__ A) {
    long i0 = (long)blockIdx.x * blockDim.x + threadIdx.x;
    long stride = (long)gridDim.x * blockDim.x;
    for (long i = i0; i < (long)Nn * Nn; i += stride) gAh[i] = __float2half_rn(A[i]);
}

// fp32 hop output -> fp16 shadow for next GEMM
__global__ void conv_X(int which) {
    const float* S = which ? g_C1T : g_X1T;
    __half* D = which ? g_C1h : g_X1h;
    int i0 = blockIdx.x * blockDim.x + threadIdx.x;
    int nth = gridDim.x * blockDim.x;
    for (int i = i0; i < NF * TST; i += nth) {
        int c = i / TST, n = i - c * TST;
        D[c * TSTH + n] = __float2half_rn(S[i]);
    }
}

__global__ void init_k() {
    int tid = blockIdx.x * blockDim.x + threadIdx.x;
    int nth = gridDim.x * blockDim.x;
    for (int j = tid; j < NF * TST; j += nth) {
        g_X0T[j] = 0.f; g_X1T[j] = 0.f; g_X2T[j] = 0.f;
        g_C0T[j] = 0.f; g_C1T[j] = 0.f; g_C2T[j] = 0.f;
    }
    for (int j = tid; j < NF * TSTH; j += nth) {
        g_X0h[j] = __half(0.f); g_X1h[j] = __half(0.f);
        g_C0h[j] = __half(0.f); g_C1h[j] = __half(0.f);
    }
    for (int j = tid; j < NU * TST; j += nth) { g_hT[j] = 0.f; g_uT[j] = 0.f; }
}

__global__ void build_enc(const float* __restrict__ inp, int tstep) {
    int tid = blockIdx.x * blockDim.x + threadIdx.x;
    int nth = gridDim.x * blockDim.x;
    for (int j = tid; j < NF * TST; j += nth) {
        int c = j / TST, n = j - c * TST;
        float v = 0.f;
        if (n < Nn) v = (c == 0) ? inp[n * TENC + tstep] : g_hT[(c - 1) * TST + n];
        g_X0T[j] = v;
        g_X0h[c * TSTH + n] = __float2half_rn(v);
        g_X1T[j] = 0.f; g_X2T[j] = 0.f;
    }
}

__global__ void build_dec0() {
    int tid = blockIdx.x * blockDim.x + threadIdx.x;
    int nth = gridDim.x * blockDim.x;
    for (int j = tid; j < NF * TST; j += nth) {
        int c = j / TST, n = j - c * TST;
        float v = 0.f;
        if (n < Nn && c > 0) v = g_hT[(c - 1) * TST + n];
        g_X0T[j] = v;
        g_X0h[c * TSTH + n] = __float2half_rn(v);
        g_X1T[j] = 0.f; g_X2T[j] = 0.f;
    }
}

__global__ void __launch_bounds__(256) gate_k(const float* __restrict__ W,
                                              const float* __restrict__ b) {
    __shared__ float sW[99 * 64];
    __shared__ float sx[99 * 32];
    const int t = threadIdx.x, lane = t & 31, w = t >> 5;
    const int rowb = blockIdx.x * 32;
    for (int j = t; j < 99 * 64; j += 256) sW[j] = W[j];
    for (int j = t; j < 99 * 32; j += 256) {
        int c = j >> 5, i = j & 31;
        const float* src = (c < 33) ? (g_X0T + c * TST)
                         : (c < 66) ? (g_X1T + (c - 33) * TST)
                                    : (g_X2T + (c - 66) * TST);
        sx[j] = src[rowb + i];
    }
    __syncthreads();

    float acc[8];
    #pragma unroll
    for (int cc = 0; cc < 8; ++cc) acc[cc] = b[8 * w + cc];
    for (int k = 0; k < 99; ++k) {
        float xv = sx[k * 32 + lane];
        const float4* wr = reinterpret_cast<const float4*>(sW + k * 64 + 8 * w);
        float4 w0 = wr[0], w1 = wr[1];
        acc[0] = fmaf(xv, w0.x, acc[0]); acc[1] = fmaf(xv, w0.y, acc[1]);
        acc[2] = fmaf(xv, w0.z, acc[2]); acc[3] = fmaf(xv, w0.w, acc[3]);
        acc[4] = fmaf(xv, w1.x, acc[4]); acc[5] = fmaf(xv, w1.y, acc[5]);
        acc[6] = fmaf(xv, w1.z, acc[6]); acc[7] = fmaf(xv, w1.w, acc[7]);
    }
    int row = rowb + lane;
    if (row < Nn) {
        #pragma unroll
        for (int cc = 0; cc < 8; ++cc) {
            int col = 8 * w + cc;
            float s = 1.f / (1.f + expf(-acc[cc]));
            if (col < 32) {
                float rh = s * g_hT[col * TST + row];
                g_C0T[(1 + col) * TST + row] = rh;
                g_C0h[(1 + col) * TSTH + row] = __float2half_rn(rh);
            } else {
                g_uT[(col - 32) * TST + row] = s;
            }
        }
        if (w == 0) {
            g_C0T[row] = g_X0T[row];
            g_C0h[row] = g_X0h[row];
        }
    }
    int tid = blockIdx.x * 256 + t, nth = gridDim.x * 256;
    for (int j = tid; j < NF * TST; j += nth) { g_C1T[j] = 0.f; g_C2T[j] = 0.f; }
}

__global__ void __launch_bounds__(256) cand_k(const float* __restrict__ W,
                                              const float* __restrict__ b) {
    __shared__ float sW[99 * 32];
    __shared__ float sx[99 * 32];
    const int t = threadIdx.x, lane = t & 31, w = t >> 5;
    const int rowb = blockIdx.x * 32;
    for (int j = t; j < 99 * 32; j += 256) sW[j] = W[j];
    for (int j = t; j < 99 * 32; j += 256) {
        int c = j >> 5, i = j & 31;
        const float* src = (c < 33) ? (g_C0T + c * TST)
                         : (c < 66) ? (g_C1T + (c - 33) * TST)
                                    : (g_C2T + (c - 66) * TST);
        sx[j] = src[rowb + i];
    }
    __syncthreads();

    float acc[4];
    #pragma unroll
    for (int cc = 0; cc < 4; ++cc) acc[cc] = b[4 * w + cc];
    for (int k = 0; k < 99; ++k) {
        float xv = sx[k * 32 + lane];
        float4 wv = *reinterpret_cast<const float4*>(sW + k * 32 + 4 * w);
        acc[0] = fmaf(xv, wv.x, acc[0]); acc[1] = fmaf(xv, wv.y, acc[1]);
        acc[2] = fmaf(xv, wv.z, acc[2]); acc[3] = fmaf(xv, wv.w, acc[3]);
    }
    int row = rowb + lane;
    if (row < Nn) {
        #pragma unroll
        for (int cc = 0; cc < 4; ++cc) {
            int col = 4 * w + cc;
            float c = tanhf(acc[cc]);
            float u = g_uT[col * TST + row];
            float h = g_hT[col * TST + row];
            g_hT[col * TST + row] = u * h + (1.f - u) * c;
        }
    }
}

__global__ void __launch_bounds__(256) dec_post(const float* __restrict__ Wp,
                                                const float* __restrict__ bp,
                                                float* __restrict__ out, int tstep) {
    int tid = blockIdx.x * 256 + threadIdx.x;
    int nth = gridDim.x * 256;
    for (int row = tid; row < Nn; row += nth) {
        float acc = bp[0];
        #pragma unroll
        for (int c = 0; c < 32; ++c) acc = fmaf(g_hT[c * TST + row], Wp[c], acc);
        out[row * TDEC + tstep] = acc;
        g_X0T[row] = acc;
        g_X0h[row] = __float2half_rn(acc);
    }
    for (int j = tid; j < NU * TST; j += nth) {
        int c = j / TST, n = j - c * TST;
        float h = g_hT[j];
        g_X0T[TST + j] = h;
        g_X0h[(1 + c) * TSTH + n] = __float2half_rn(h);
    }
    for (int j = tid; j < NF * TST; j += nth) { g_X1T[j] = 0.f; g_X2T[j] = 0.f; }
}

// ============================================================================
// Host launch sequence
// ============================================================================
extern "C" void kernel_launch(void* const* d_in, const int* in_sizes, int n_in,
                              void* d_out, int out_size) {
    const float* inputs = (const float*)d_in[0];
    const float* adj    = (const float*)d_in[2];
    const float* enc_Wg = (const float*)d_in[3];
    const float* enc_bg = (const float*)d_in[4];
    const float* enc_Wc = (const float*)d_in[5];
    const float* enc_bc = (const float*)d_in[6];
    const float* dec_Wg = (const float*)d_in[7];
    const float* dec_bg = (const float*)d_in[8];
    const float* dec_Wc = (const float*)d_in[9];
    const float* dec_bc = (const float*)d_in[10];
    const float* dec_Wp = (const float*)d_in[11];
    const float* dec_bp = (const float*)d_in[12];
    float* out = (float*)d_out;

    cudaFuncSetAttribute(gemm_mma, cudaFuncAttributeMaxDynamicSharedMemorySize, DSMEM);
    cudaFuncSetAttribute(gemm_mma, cudaFuncAttributePreferredSharedMemoryCarveout, 100);

    conv_A<<<1024, 256>>>(adj);
    init_k<<<256, 256>>>();

    for (int t = 0; t < TENC; ++t) {
        build_enc<<<256, 256>>>(inputs, t);
        gemm_mma<<<GGRID, 128, DSMEM>>>(0);
        conv_X<<<128, 256>>>(0);
        gemm_mma<<<GGRID, 128, DSMEM>>>(1);
        gate_k<<<157, 256>>>(enc_Wg, enc_bg);
        gemm_mma<<<GGRID, 128, DSMEM>>>(2);
        conv_X<<<128, 256>>>(1);
        gemm_mma<<<GGRID, 128, DSMEM>>>(3);
        cand_k<<<157, 256>>>(enc_Wc, enc_bc);
    }

    build_dec0<<<256, 256>>>();
    for (int t = 0; t < TDEC; ++t) {
        gemm_mma<<<GGRID, 128, DSMEM>>>(0);
        conv_X<<<128, 256>>>(0);
        gemm_mma<<<GGRID, 128, DSMEM>>>(1);
        gate_k<<<157, 256>>>(dec_Wg, dec_bg);
        gemm_mma<<<GGRID, 128, DSMEM>>>(2);
        conv_X<<<128, 256>>>(1);
        gemm_mma<<<GGRID, 128, DSMEM>>>(3);
        cand_k<<<157, 256>>>(dec_Wc, dec_bc);
        dec_post<<<157, 256>>>(dec_Wp, dec_bp, out, t);
    }
}